// round 16
// baseline (speedup 1.0000x reference)
#include <cuda_runtime.h>
#include <cuda_bf16.h>
#include <cstdint>

#define NNODES 50000
#define EEDGES 1600000
#define DHID 128
#define DNF 128
#define DNG 64
#define LN2 0.69314718055994530942f
#define FPI 3.14159265358979323846f

typedef unsigned long long ull;
typedef unsigned int uint;

// Scratch (static device arrays: allocation-free per harness rules)
__device__ float g_h[(size_t)NNODES * DNF];    // x @ lin1_w
__device__ float g_agg[(size_t)NNODES * DNF];  // segment_sum accumulator
__device__ int   g_cnt;                        // compacted edge count
__device__ int   g_hist[NNODES];               // per-dst edge count
__device__ int   g_off[NNODES];                // exclusive prefix (mutated by scatter)
__device__ int4  g_edge[EEDGES + 128];         // dst-sorted {eid, src, dst, C-bits} (padded)

// ---------------- helpers ----------------
__device__ __forceinline__ float ssp_f(float v) {
    return fmaxf(v, 0.0f) + __logf(1.0f + __expf(-fabsf(v))) - LN2;
}
__device__ __forceinline__ void red_add_v4(float* p, float a, float b, float c, float d) {
    asm volatile("red.global.add.v4.f32 [%0], {%1, %2, %3, %4};"
                 :: "l"(p), "f"(a), "f"(b), "f"(c), "f"(d) : "memory");
}
__device__ __forceinline__ void red_add_v2(float* p, float a, float b) {
    asm volatile("red.global.add.v2.f32 [%0], {%1, %2};"
                 :: "l"(p), "f"(a), "f"(b) : "memory");
}
__device__ __forceinline__ ull pack2(float a) {
    ull r;
    asm("mov.b64 %0, {%1, %1};" : "=l"(r) : "f"(a));
    return r;
}
__device__ __forceinline__ float2 unpack2(ull v) {
    float2 f;
    asm("mov.b64 {%0, %1}, %2;" : "=f"(f.x), "=f"(f.y) : "l"(v));
    return f;
}
__device__ __forceinline__ void fma2(ull& d, ull a, ull b) {
    asm("fma.rn.f32x2 %0, %1, %2, %0;" : "+l"(d) : "l"(a), "l"(b));
}
__device__ __forceinline__ float4 ldcs4(const float* p) {
    float4 v;
    asm volatile("ld.global.cs.v4.f32 {%0,%1,%2,%3}, [%4];"
                 : "=f"(v.x), "=f"(v.y), "=f"(v.z), "=f"(v.w) : "l"(p));
    return v;
}

// bf16 mma.sync: D(16x8,f32) += A(16x16)B(16x8)
__device__ __forceinline__ void mma_bf16(float d[4], uint a0, uint a1, uint a2, uint a3,
                                         uint b0, uint b1) {
    asm volatile(
        "mma.sync.aligned.m16n8k16.row.col.f32.bf16.bf16.f32 "
        "{%0,%1,%2,%3}, {%4,%5,%6,%7}, {%8,%9}, {%0,%1,%2,%3};"
        : "+f"(d[0]), "+f"(d[1]), "+f"(d[2]), "+f"(d[3])
        : "r"(a0), "r"(a1), "r"(a2), "r"(a3), "r"(b0), "r"(b1));
}
__device__ __forceinline__ void ldsm4(uint& r0, uint& r1, uint& r2, uint& r3, uint addr) {
    asm volatile("ldmatrix.sync.aligned.m8n8.x4.shared.b16 {%0,%1,%2,%3}, [%4];"
                 : "=r"(r0), "=r"(r1), "=r"(r2), "=r"(r3) : "r"(addr));
}

// split (x,y) -> packed bf16 hi pair + lo pair
__device__ __forceinline__ void splitpair(float x, float y, uint& h, uint& l) {
    __nv_bfloat162 hh = __floats2bfloat162_rn(x, y);
    float2 hf = __bfloat1622float2(hh);
    __nv_bfloat162 ll = __floats2bfloat162_rn(x - hf.x, y - hf.y);
    h = *reinterpret_cast<uint*>(&hh);
    l = *reinterpret_cast<uint*>(&ll);
}

// ---- scalar microkernels for k_proj / k_out ----
template <int K>
__device__ __forceinline__ void mm8x8g(const float* __restrict__ As,
                                       const float* __restrict__ Bg,
                                       int rg2, int c0, ull acc[4][8]) {
#pragma unroll 4
    for (int k = 0; k < K; ++k) {
        const float* ar = As + k * 130 + rg2;
        ull a0 = *(const ull*)(ar);
        ull a1 = *(const ull*)(ar + 32);
        ull a2 = *(const ull*)(ar + 64);
        ull a3 = *(const ull*)(ar + 96);
        const float4* bp = (const float4*)(Bg + k * 128 + c0);
        float4 b0 = __ldg(bp);
        float4 b1 = __ldg(bp + 1);
        ull bb[8] = {pack2(b0.x), pack2(b0.y), pack2(b0.z), pack2(b0.w),
                     pack2(b1.x), pack2(b1.y), pack2(b1.z), pack2(b1.w)};
#pragma unroll
        for (int c = 0; c < 8; ++c) {
            fma2(acc[0][c], a0, bb[c]);
            fma2(acc[1][c], a1, bb[c]);
            fma2(acc[2][c], a2, bb[c]);
            fma2(acc[3][c], a3, bb[c]);
        }
    }
}
template <int K>
__device__ __forceinline__ void mm4x8(const float* __restrict__ As,
                                      const float* __restrict__ Bs,
                                      int rg, int c0, ull acc[4][4]) {
#pragma unroll 4
    for (int k = 0; k < K; ++k) {
        const float* ar = As + k * 130 + rg;
        ull a0 = pack2(ar[0]);
        ull a1 = pack2(ar[32]);
        ull a2 = pack2(ar[64]);
        ull a3 = pack2(ar[96]);
        const float* br = Bs + k * 128 + c0;
        ulonglong2 b01 = *(const ulonglong2*)br;
        ulonglong2 b23 = *(const ulonglong2*)(br + 4);
        ull bb[4] = {b01.x, b01.y, b23.x, b23.y};
#pragma unroll
        for (int p = 0; p < 4; ++p) {
            fma2(acc[0][p], a0, bb[p]);
            fma2(acc[1][p], a1, bb[p]);
            fma2(acc[2][p], a2, bb[p]);
            fma2(acc[3][p], a3, bb[p]);
        }
    }
}

// ---------------- sort chain ----------------
extern "C" __global__ void __launch_bounds__(256)
k_count(const int* __restrict__ ei, const float* __restrict__ elen) {
    const int stride = gridDim.x * blockDim.x;
    for (int i = blockIdx.x * blockDim.x + threadIdx.x; i < EEDGES; i += stride) {
        float L = elen[i];
        if (L <= 10.0f && L >= 0.0f)
            atomicAdd(&g_hist[ei[EEDGES + i]], 1);
    }
}

extern "C" __global__ void __launch_bounds__(1024)
k_scan() {
    __shared__ int wsum[32];
    const int tid = threadIdx.x;
    const int lane = tid & 31, wid = tid >> 5;
    int running = 0;
    for (int base = 0; base < NNODES; base += 1024) {
        int idx = base + tid;
        int v = (idx < NNODES) ? g_hist[idx] : 0;
        int x = v;
#pragma unroll
        for (int o = 1; o < 32; o <<= 1) {
            int t = __shfl_up_sync(0xffffffffu, x, o);
            if (lane >= o) x += t;
        }
        if (lane == 31) wsum[wid] = x;
        __syncthreads();
        if (wid == 0) {
            int w = wsum[lane];
#pragma unroll
            for (int o = 1; o < 32; o <<= 1) {
                int t = __shfl_up_sync(0xffffffffu, w, o);
                if (lane >= o) w += t;
            }
            wsum[lane] = w;
        }
        __syncthreads();
        int woff = wid ? wsum[wid - 1] : 0;
        if (idx < NNODES) g_off[idx] = running + woff + x - v;
        running += wsum[31];
        __syncthreads();
    }
    if (tid == 0) g_cnt = running;
}

extern "C" __global__ void __launch_bounds__(256)
k_scatter(const int* __restrict__ ei, const float* __restrict__ elen) {
    const int stride = gridDim.x * blockDim.x;
    for (int i = blockIdx.x * blockDim.x + threadIdx.x; i < EEDGES; i += stride) {
        float L = elen[i];
        if (L <= 10.0f && L >= 0.0f) {
            int d = ei[EEDGES + i];
            int pos = atomicAdd(&g_off[d], 1);
            float C = 0.5f * (__cosf(L * (FPI / 10.0f)) + 1.0f);
            g_edge[pos] = make_int4(i, ei[i], d, __float_as_int(C));
        }
    }
}

// dummy so ncu's -s5 window (6th launch) lands on k_edge
extern "C" __global__ void k_nop() {}

// ---------------- Kernel 1: h = x @ lin1_w, zero g_agg + g_hist ----------------
extern "C" __global__ void __launch_bounds__(256, 2)
k_proj_zero(const float* __restrict__ x, const float* __restrict__ w1) {
    extern __shared__ float smf[];
    float* sX = smf;
    const int tid = threadIdx.x;
    const int cg = tid >> 4, rg = tid & 15;
    const int c0 = cg * 8, rg2 = rg * 2;

    const int ntiles = (NNODES + 127) / 128;
    for (int tile = blockIdx.x; tile < ntiles; tile += gridDim.x) {
        const int r0 = tile * 128;
        __syncthreads();
        {
            int e = tid >> 1, k0 = (tid & 1) << 6;
            int r = r0 + e;
            if (r < NNODES) {
                const float* src = x + (size_t)r * DHID + k0;
#pragma unroll
                for (int i = 0; i < 16; ++i) {
                    float4 v = ldcs4(src + 4 * i);
                    int k = k0 + 4 * i;
                    sX[(k + 0) * 130 + e] = v.x;
                    sX[(k + 1) * 130 + e] = v.y;
                    sX[(k + 2) * 130 + e] = v.z;
                    sX[(k + 3) * 130 + e] = v.w;
                }
            }
        }
        __syncthreads();
        ull acc[4][8];
#pragma unroll
        for (int j = 0; j < 4; ++j)
#pragma unroll
            for (int c = 0; c < 8; ++c) acc[j][c] = 0ull;
        mm8x8g<DHID>(sX, w1, rg2, c0, acc);
#pragma unroll
        for (int j = 0; j < 4; ++j) {
            int r = r0 + rg2 + 32 * j;
            float2 v0 = unpack2(acc[j][0]), v1 = unpack2(acc[j][1]);
            float2 v2 = unpack2(acc[j][2]), v3 = unpack2(acc[j][3]);
            float2 v4 = unpack2(acc[j][4]), v5 = unpack2(acc[j][5]);
            float2 v6 = unpack2(acc[j][6]), v7 = unpack2(acc[j][7]);
            if (r < NNODES) {
                *(float4*)(g_h + (size_t)r * DNF + c0) = make_float4(v0.x, v1.x, v2.x, v3.x);
                *(float4*)(g_h + (size_t)r * DNF + c0 + 4) = make_float4(v4.x, v5.x, v6.x, v7.x);
                *(float4*)(g_agg + (size_t)r * DNF + c0) = make_float4(0.f, 0.f, 0.f, 0.f);
                *(float4*)(g_agg + (size_t)r * DNF + c0 + 4) = make_float4(0.f, 0.f, 0.f, 0.f);
                if (cg == 0) g_hist[r] = 0;
            }
            if (r + 1 < NNODES) {
                *(float4*)(g_h + (size_t)(r + 1) * DNF + c0) = make_float4(v0.y, v1.y, v2.y, v3.y);
                *(float4*)(g_h + (size_t)(r + 1) * DNF + c0 + 4) = make_float4(v4.y, v5.y, v6.y, v7.y);
                *(float4*)(g_agg + (size_t)(r + 1) * DNF + c0) = make_float4(0.f, 0.f, 0.f, 0.f);
                *(float4*)(g_agg + (size_t)(r + 1) * DNF + c0 + 4) = make_float4(0.f, 0.f, 0.f, 0.f);
                if (cg == 0) g_hist[r + 1] = 0;
            }
        }
    }
}

// ------- Kernel 2: HMMA edge MLP (fragment-direct epilogue, 3 barriers/tile) -------
#define ST64 72
#define ST128 136
#define OFF_B1  0
#define OFF_B2  512
#define OFF_W1H 1024
#define OFF_W1L (OFF_W1H + 128 * ST64 * 2)
#define OFF_W2H (OFF_W1L + 128 * ST64 * 2)
#define OFF_W2L (OFF_W2H + 128 * ST128 * 2)
#define OFF_SAH (OFF_W2L + 128 * ST128 * 2)
#define OFF_SAL (OFF_SAH + 128 * ST64 * 2)
#define OFF_STH (OFF_SAL + 128 * ST64 * 2)
#define OFF_STL (OFF_STH + 128 * ST128 * 2)
#define SMEM_EDGE (OFF_STL + 128 * ST128 * 2)   // 214016 B

extern "C" __global__ void __launch_bounds__(1024, 1)
k_edge(const float* __restrict__ edge_attr,
       const float* __restrict__ w1, const float* __restrict__ b1,
       const float* __restrict__ w2, const float* __restrict__ b2) {
    extern __shared__ __align__(16) char sm[];
    float* sB1 = (float*)(sm + OFF_B1);
    float* sB2 = (float*)(sm + OFF_B2);

    const int tid = threadIdx.x;
    const int lane = tid & 31, wid = tid >> 5;
    const int g = lane >> 2, t = lane & 3;
    const int mw = (wid & 7) * 16;              // row strip (8 strips)
    const int nw = (wid >> 3) * 32;             // col quarter (4 quarters)

    // ldmatrix lane addressing: A/T fragments (row-major 16x16)
    const int arow = mw + (lane & 7) + ((lane >> 3) & 1) * 8;
    const int acol = ((lane >> 4) & 1) * 8;
    const uint sbase = (uint)__cvta_generic_to_shared(sm);
    const uint aSAH = sbase + OFF_SAH + (uint)((arow * ST64 + acol) * 2);
    const uint aSAL = sbase + OFF_SAL + (uint)((arow * ST64 + acol) * 2);
    const uint aSTH = sbase + OFF_STH + (uint)((arow * ST128 + acol) * 2);
    const uint aSTL = sbase + OFF_STL + (uint)((arow * ST128 + acol) * 2);

    // ldmatrix lane addressing: B fragments ([n][k] storage)
    const int bn = (lane & 7) + ((lane >> 4) & 1) * 8;
    const int bk = ((lane >> 3) & 1) * 8;
    const uint aW1H0 = sbase + OFF_W1H + (uint)(((nw + bn) * ST64 + bk) * 2);
    const uint aW1H1 = sbase + OFF_W1H + (uint)(((nw + 16 + bn) * ST64 + bk) * 2);
    const uint aW1L0 = sbase + OFF_W1L + (uint)(((nw + bn) * ST64 + bk) * 2);
    const uint aW1L1 = sbase + OFF_W1L + (uint)(((nw + 16 + bn) * ST64 + bk) * 2);
    const uint aW2H0 = sbase + OFF_W2H + (uint)(((nw + bn) * ST128 + bk) * 2);
    const uint aW2H1 = sbase + OFF_W2H + (uint)(((nw + 16 + bn) * ST128 + bk) * 2);
    const uint aW2L0 = sbase + OFF_W2L + (uint)(((nw + bn) * ST128 + bk) * 2);
    const uint aW2L1 = sbase + OFF_W2L + (uint)(((nw + 16 + bn) * ST128 + bk) * 2);

    // ---- prologue: weights (transposed, hi/lo split) + biases ----
    for (int idx = tid; idx < DNG * DNF; idx += 1024) {
        int k = idx >> 7, f = idx & 127;
        float v = w1[idx];
        __nv_bfloat16 h = __float2bfloat16(v);
        __nv_bfloat16 l = __float2bfloat16(v - __bfloat162float(h));
        ((__nv_bfloat16*)(sm + OFF_W1H))[f * ST64 + k] = h;
        ((__nv_bfloat16*)(sm + OFF_W1L))[f * ST64 + k] = l;
    }
    for (int idx = tid; idx < DNF * DNF; idx += 1024) {
        int f1 = idx >> 7, f2 = idx & 127;
        float v = w2[idx];
        __nv_bfloat16 h = __float2bfloat16(v);
        __nv_bfloat16 l = __float2bfloat16(v - __bfloat162float(h));
        ((__nv_bfloat16*)(sm + OFF_W2H))[f2 * ST128 + f1] = h;
        ((__nv_bfloat16*)(sm + OFF_W2L))[f2 * ST128 + f1] = l;
    }
    if (tid < DNF) { sB1[tid] = b1[tid]; sB2[tid] = b2[tid]; }

    const int cnt = g_cnt;
    const int ntiles = (cnt + 127) >> 7;
    const int stride = gridDim.x;

    const int le = tid >> 3, lk0 = (tid & 7) << 3;   // A-load: 8 floats/thread

    auto ldg_tile = [&](int tile, float4 pf[2]) {
        int gi = (tile << 7) + le;
        int eid = (gi < cnt) ? __ldg(&g_edge[gi]).x : 0;
        const float* src = edge_attr + (size_t)eid * DNG + lk0;
        pf[0] = ldcs4(src);
        pf[1] = ldcs4(src + 4);
    };
    auto sts_tile = [&](const float4 pf[2]) {
        uint* dh = (uint*)(sm + OFF_SAH) + (le * ST64 + lk0) / 2;
        uint* dl = (uint*)(sm + OFF_SAL) + (le * ST64 + lk0) / 2;
#pragma unroll
        for (int i = 0; i < 2; ++i) {
            uint h0, l0, h1, l1;
            splitpair(pf[i].x, pf[i].y, h0, l0);
            splitpair(pf[i].z, pf[i].w, h1, l1);
            dh[2 * i] = h0; dh[2 * i + 1] = h1;
            dl[2 * i] = l0; dl[2 * i + 1] = l1;
        }
    };

    int tile = blockIdx.x;
    if (tile < ntiles) {
        float4 pf[2];
        ldg_tile(tile, pf);
        sts_tile(pf);
    }
    __syncthreads();

    for (; tile < ntiles; tile += stride) {
        const int eg0 = tile << 7;

        // ---- GEMM1 (K=64) ----
        float d1[4][4];
#pragma unroll
        for (int nt = 0; nt < 4; ++nt)
#pragma unroll
            for (int q = 0; q < 4; ++q) d1[nt][q] = 0.0f;
#pragma unroll
        for (int kc = 0; kc < 4; ++kc) {
            uint ah0, ah1, ah2, ah3, al0, al1, al2, al3;
            ldsm4(ah0, ah1, ah2, ah3, aSAH + kc * 32);
            ldsm4(al0, al1, al2, al3, aSAL + kc * 32);
#pragma unroll
            for (int p = 0; p < 2; ++p) {
                uint bh0, bh1, bh2, bh3, bl0v, bl1v, bl2v, bl3v;
                ldsm4(bh0, bh1, bh2, bh3, (p ? aW1H1 : aW1H0) + kc * 32);
                ldsm4(bl0v, bl1v, bl2v, bl3v, (p ? aW1L1 : aW1L0) + kc * 32);
                mma_bf16(d1[2 * p], ah0, ah1, ah2, ah3, bh0, bh1);
                mma_bf16(d1[2 * p], al0, al1, al2, al3, bh0, bh1);
                mma_bf16(d1[2 * p], ah0, ah1, ah2, ah3, bl0v, bl1v);
                mma_bf16(d1[2 * p + 1], ah0, ah1, ah2, ah3, bh2, bh3);
                mma_bf16(d1[2 * p + 1], al0, al1, al2, al3, bh2, bh3);
                mma_bf16(d1[2 * p + 1], ah0, ah1, ah2, ah3, bl2v, bl3v);
            }
        }
        __syncthreads();   // bar1: sA reads done; prev GEMM2's sT reads done

        // ---- prefetch next tile's A ----
        const int tnext = tile + stride;
        const bool have = tnext < ntiles;
        float4 pf[2];
        if (have) ldg_tile(tnext, pf);

        // ---- ssp(D1 + b1) -> sT hi/lo ----
#pragma unroll
        for (int nt = 0; nt < 4; ++nt) {
            int c = nw + nt * 8 + 2 * t;
            float b0v = sB1[c], b1v = sB1[c + 1];
            uint h, l;
            splitpair(ssp_f(d1[nt][0] + b0v), ssp_f(d1[nt][1] + b1v), h, l);
            *(uint*)(sm + OFF_STH + ((mw + g) * ST128 + c) * 2) = h;
            *(uint*)(sm + OFF_STL + ((mw + g) * ST128 + c) * 2) = l;
            splitpair(ssp_f(d1[nt][2] + b0v), ssp_f(d1[nt][3] + b1v), h, l);
            *(uint*)(sm + OFF_STH + ((mw + g + 8) * ST128 + c) * 2) = h;
            *(uint*)(sm + OFF_STL + ((mw + g + 8) * ST128 + c) * 2) = l;
        }
        __syncthreads();   // bar2: sT ready

        // ---- GEMM2 (K=128) ----
        float d2[4][4];
#pragma unroll
        for (int nt = 0; nt < 4; ++nt)
#pragma unroll
            for (int q = 0; q < 4; ++q) d2[nt][q] = 0.0f;
#pragma unroll
        for (int kc = 0; kc < 8; ++kc) {
            uint ah0, ah1, ah2, ah3, al0, al1, al2, al3;
            ldsm4(ah0, ah1, ah2, ah3, aSTH + kc * 32);
            ldsm4(al0, al1, al2, al3, aSTL + kc * 32);
#pragma unroll
            for (int p = 0; p < 2; ++p) {
                uint bh0, bh1, bh2, bh3, bl0v, bl1v, bl2v, bl3v;
                ldsm4(bh0, bh1, bh2, bh3, (p ? aW2H1 : aW2H0) + kc * 32);
                ldsm4(bl0v, bl1v, bl2v, bl3v, (p ? aW2L1 : aW2L0) + kc * 32);
                mma_bf16(d2[2 * p], ah0, ah1, ah2, ah3, bh0, bh1);
                mma_bf16(d2[2 * p], al0, al1, al2, al3, bh0, bh1);
                mma_bf16(d2[2 * p], ah0, ah1, ah2, ah3, bl0v, bl1v);
                mma_bf16(d2[2 * p + 1], ah0, ah1, ah2, ah3, bh2, bh3);
                mma_bf16(d2[2 * p + 1], al0, al1, al2, al3, bh2, bh3);
                mma_bf16(d2[2 * p + 1], ah0, ah1, ah2, ah3, bl2v, bl3v);
            }
        }

        // ---- store prefetched A (sA free since bar1) ----
        if (have) sts_tile(pf);
        __syncthreads();   // bar3: sA ready for next GEMM1; sT reads done for next ssp

        // ---- epilogue DIRECTLY from d2 fragments (overlaps next GEMM1) ----
        {
            int eA = eg0 + mw + g;
            int eB = eA + 8;
            int4 edA = __ldg(&g_edge[eA]);
            int4 edB = __ldg(&g_edge[eB]);
            float cvA = __int_as_float(edA.w);
            float cvB = __int_as_float(edB.w);
            bool okA = (eA < cnt) && (cvA != 0.0f);
            bool okB = (eB < cnt) && (cvB != 0.0f);
            const float* hA = g_h + (size_t)edA.y * DNF;
            const float* hB = g_h + (size_t)edB.y * DNF;
            float mA[8], mB[8];
#pragma unroll
            for (int nt = 0; nt < 4; ++nt) {
                int c = nw + nt * 8 + 2 * t;
                float2 bb = *(const float2*)(sB2 + c);
                if (okA) {
                    float2 hv = __ldg((const float2*)(hA + c));
                    mA[2 * nt] = (d2[nt][0] + bb.x) * cvA * hv.x;
                    mA[2 * nt + 1] = (d2[nt][1] + bb.y) * cvA * hv.y;
                }
                if (okB) {
                    float2 hv = __ldg((const float2*)(hB + c));
                    mB[2 * nt] = (d2[nt][2] + bb.x) * cvB * hv.x;
                    mB[2 * nt + 1] = (d2[nt][3] + bb.y) * cvB * hv.y;
                }
            }
            if (okA && okB && edA.z == edB.z) {
                float* dp = g_agg + (size_t)edA.z * DNF;
#pragma unroll
                for (int nt = 0; nt < 4; ++nt) {
                    int c = nw + nt * 8 + 2 * t;
                    red_add_v2(dp + c, mA[2 * nt] + mB[2 * nt], mA[2 * nt + 1] + mB[2 * nt + 1]);
                }
            } else {
                if (okA) {
                    float* dp = g_agg + (size_t)edA.z * DNF;
#pragma unroll
                    for (int nt = 0; nt < 4; ++nt) {
                        int c = nw + nt * 8 + 2 * t;
                        red_add_v2(dp + c, mA[2 * nt], mA[2 * nt + 1]);
                    }
                }
                if (okB) {
                    float* dp = g_agg + (size_t)edB.z * DNF;
#pragma unroll
                    for (int nt = 0; nt < 4; ++nt) {
                        int c = nw + nt * 8 + 2 * t;
                        red_add_v2(dp + c, mB[2 * nt], mB[2 * nt + 1]);
                    }
                }
            }
        }
        // epilogue is register/global only -> next GEMM1 proceeds without a barrier.
    }
}

// -------- Kernel 3: out = ssp(agg@lin2_w + lin2_b) @ lin_w + lin_b --------
extern "C" __global__ void __launch_bounds__(512, 1)
k_out(const float* __restrict__ w2, const float* __restrict__ b2,
      const float* __restrict__ w3, const float* __restrict__ b3,
      float* __restrict__ out) {
    extern __shared__ float smf[];
    float* sW2 = smf;
    float* sW3 = sW2 + DNF * DHID;
    float* sA  = sW3 + DHID * DHID;
    float* sB2 = sA + DNF * 130;
    float* sB3 = sB2 + 128;

    const int tid = threadIdx.x;
    const int rg = tid & 31, cg = tid >> 5;
    const int c0 = cg * 8;

    for (int i = tid; i < DNF * DHID / 4; i += 512)
        ((float4*)sW2)[i] = ((const float4*)w2)[i];
    for (int i = tid; i < DHID * DHID / 4; i += 512)
        ((float4*)sW3)[i] = ((const float4*)w3)[i];
    if (tid < DHID) { sB2[tid] = b2[tid]; sB3[tid] = b3[tid]; }

    const int ntiles = (NNODES + 127) / 128;
    for (int tile = blockIdx.x; tile < ntiles; tile += gridDim.x) {
        const int r0 = tile * 128;
        __syncthreads();
        {
            int e = tid >> 2, k0 = (tid & 3) << 5;
            int r = r0 + e;
            const float* src = g_agg + (size_t)r * DNF + k0;
#pragma unroll
            for (int i = 0; i < 8; ++i) {
                float4 v = (r < NNODES) ? ldcs4(src + 4 * i) : make_float4(0.f, 0.f, 0.f, 0.f);
                int k = k0 + 4 * i;
                sA[(k + 0) * 130 + e] = v.x;
                sA[(k + 1) * 130 + e] = v.y;
                sA[(k + 2) * 130 + e] = v.z;
                sA[(k + 3) * 130 + e] = v.w;
            }
        }
        __syncthreads();

        ull acc[4][4];
#pragma unroll
        for (int j = 0; j < 4; ++j)
#pragma unroll
            for (int p = 0; p < 4; ++p) acc[j][p] = 0ull;
        mm4x8<DNF>(sA, sW2, rg, c0, acc);
        __syncthreads();

#pragma unroll
        for (int p = 0; p < 4; ++p) {
            float bx = sB2[c0 + 2 * p], by = sB2[c0 + 2 * p + 1];
#pragma unroll
            for (int j = 0; j < 4; ++j) {
                float2 v = unpack2(acc[j][p]);
                int row = rg + 32 * j;
                sA[(c0 + 2 * p) * 130 + row] = ssp_f(v.x + bx);
                sA[(c0 + 2 * p + 1) * 130 + row] = ssp_f(v.y + by);
            }
        }
        __syncthreads();

#pragma unroll
        for (int j = 0; j < 4; ++j)
#pragma unroll
            for (int p = 0; p < 4; ++p) acc[j][p] = 0ull;
        mm4x8<DHID>(sA, sW3, rg, c0, acc);

#pragma unroll
        for (int j = 0; j < 4; ++j) {
            int r = r0 + rg + 32 * j;
            if (r < NNODES) {
                float2 v0 = unpack2(acc[j][0]), v1 = unpack2(acc[j][1]);
                float2 v2 = unpack2(acc[j][2]), v3 = unpack2(acc[j][3]);
                *(float4*)(out + (size_t)r * DHID + c0) =
                    make_float4(v0.x + sB3[c0 + 0], v0.y + sB3[c0 + 1],
                                v1.x + sB3[c0 + 2], v1.y + sB3[c0 + 3]);
                *(float4*)(out + (size_t)r * DHID + c0 + 4) =
                    make_float4(v2.x + sB3[c0 + 4], v2.y + sB3[c0 + 5],
                                v3.x + sB3[c0 + 6], v3.y + sB3[c0 + 7]);
            }
        }
    }
}

extern "C" void kernel_launch(void* const* d_in, const int* in_sizes, int n_in,
                              void* d_out, int out_size) {
    const float* x      = (const float*)d_in[0];
    const int*   ei     = (const int*)d_in[1];
    const float* elen   = (const float*)d_in[2];
    const float* eattr  = (const float*)d_in[3];
    const float* lin1_w = (const float*)d_in[4];
    const float* nn_w1  = (const float*)d_in[5];
    const float* nn_b1  = (const float*)d_in[6];
    const float* nn_w2  = (const float*)d_in[7];
    const float* nn_b2  = (const float*)d_in[8];
    const float* lin2_w = (const float*)d_in[9];
    const float* lin2_b = (const float*)d_in[10];
    const float* lin_w  = (const float*)d_in[11];
    const float* lin_b  = (const float*)d_in[12];
    float* out = (float*)d_out;

    size_t sm1 = (size_t)(DHID * 130) * 4;
    size_t sm3 = (size_t)(DNF * DHID + DHID * DHID + DNF * 130 + 2 * 128) * 4;

    cudaFuncSetAttribute(k_proj_zero, cudaFuncAttributeMaxDynamicSharedMemorySize, (int)sm1);
    cudaFuncSetAttribute(k_edge, cudaFuncAttributeMaxDynamicSharedMemorySize, SMEM_EDGE);
    cudaFuncSetAttribute(k_out, cudaFuncAttributeMaxDynamicSharedMemorySize, (int)sm3);

    k_proj_zero<<<304, 256, sm1>>>(x, lin1_w);   // 1
    k_count<<<304, 256>>>(ei, elen);             // 2
    k_scan<<<1, 1024>>>();                       // 3
    k_scatter<<<304, 256>>>(ei, elen);           // 4
    k_nop<<<1, 32>>>();                          // 5 (aligns ncu -s5 capture onto k_edge)
    k_edge<<<152, 1024, SMEM_EDGE>>>(eattr, nn_w1, nn_b1, nn_w2, nn_b2);  // 6 <- profiled
    k_out<<<152, 512, sm3>>>(lin2_w, lin2_b, lin_w, lin_b, out);
}

// round 17
// speedup vs baseline: 1.1653x; 1.1653x over previous
#include <cuda_runtime.h>
#include <cuda_fp16.h>
#include <cstdint>

#define NNODES 50000
#define EEDGES 1600000
#define DHID 128
#define DNF 128
#define DNG 64
#define LN2 0.69314718055994530942f
#define FPI 3.14159265358979323846f

typedef unsigned long long ull;
typedef unsigned int uint;

// Scratch (static device arrays: allocation-free per harness rules)
__device__ float g_h[(size_t)NNODES * DNF];    // x @ lin1_w
__device__ float g_agg[(size_t)NNODES * DNF];  // segment_sum accumulator
__device__ int   g_cnt;                        // compacted edge count
__device__ int   g_hist[NNODES];               // per-dst edge count
__device__ int   g_off[NNODES];                // exclusive prefix (mutated by scatter)
__device__ int4  g_edge[EEDGES + 128];         // dst-sorted {eid, src, dst, C-bits} (padded)

// ---------------- helpers ----------------
__device__ __forceinline__ float ssp_f(float v) {
    return fmaxf(v, 0.0f) + __logf(1.0f + __expf(-fabsf(v))) - LN2;
}
__device__ __forceinline__ void red_add_v4(float* p, float a, float b, float c, float d) {
    asm volatile("red.global.add.v4.f32 [%0], {%1, %2, %3, %4};"
                 :: "l"(p), "f"(a), "f"(b), "f"(c), "f"(d) : "memory");
}
__device__ __forceinline__ ull pack2(float a) {
    ull r;
    asm("mov.b64 %0, {%1, %1};" : "=l"(r) : "f"(a));
    return r;
}
__device__ __forceinline__ float2 unpack2(ull v) {
    float2 f;
    asm("mov.b64 {%0, %1}, %2;" : "=f"(f.x), "=f"(f.y) : "l"(v));
    return f;
}
__device__ __forceinline__ void fma2(ull& d, ull a, ull b) {
    asm("fma.rn.f32x2 %0, %1, %2, %0;" : "+l"(d) : "l"(a), "l"(b));
}
__device__ __forceinline__ float4 ldcs4(const float* p) {
    float4 v;
    asm volatile("ld.global.cs.v4.f32 {%0,%1,%2,%3}, [%4];"
                 : "=f"(v.x), "=f"(v.y), "=f"(v.z), "=f"(v.w) : "l"(p));
    return v;
}
__device__ __forceinline__ float4 ldcg4(const float* p) {
    float4 v;
    asm volatile("ld.global.cg.v4.f32 {%0,%1,%2,%3}, [%4];"
                 : "=f"(v.x), "=f"(v.y), "=f"(v.z), "=f"(v.w) : "l"(p));
    return v;
}

// fp16 mma.sync: D(16x8,f32) += A(16x16,f16)B(16x8,f16)
__device__ __forceinline__ void mma_f16(float d[4], uint a0, uint a1, uint a2, uint a3,
                                        uint b0, uint b1) {
    asm volatile(
        "mma.sync.aligned.m16n8k16.row.col.f32.f16.f16.f32 "
        "{%0,%1,%2,%3}, {%4,%5,%6,%7}, {%8,%9}, {%0,%1,%2,%3};"
        : "+f"(d[0]), "+f"(d[1]), "+f"(d[2]), "+f"(d[3])
        : "r"(a0), "r"(a1), "r"(a2), "r"(a3), "r"(b0), "r"(b1));
}
__device__ __forceinline__ void ldsm4(uint& r0, uint& r1, uint& r2, uint& r3, uint addr) {
    asm volatile("ldmatrix.sync.aligned.m8n8.x4.shared.b16 {%0,%1,%2,%3}, [%4];"
                 : "=r"(r0), "=r"(r1), "=r"(r2), "=r"(r3) : "r"(addr));
}

__device__ __forceinline__ uint h2bits(float x, float y) {
    __half2 h = __floats2half2_rn(x, y);
    return *reinterpret_cast<uint*>(&h);
}

// ---- scalar microkernels for k_proj / k_out ----
template <int K>
__device__ __forceinline__ void mm8x8g(const float* __restrict__ As,
                                       const float* __restrict__ Bg,
                                       int rg2, int c0, ull acc[4][8]) {
#pragma unroll 4
    for (int k = 0; k < K; ++k) {
        const float* ar = As + k * 130 + rg2;
        ull a0 = *(const ull*)(ar);
        ull a1 = *(const ull*)(ar + 32);
        ull a2 = *(const ull*)(ar + 64);
        ull a3 = *(const ull*)(ar + 96);
        const float4* bp = (const float4*)(Bg + k * 128 + c0);
        float4 b0 = __ldg(bp);
        float4 b1 = __ldg(bp + 1);
        ull bb[8] = {pack2(b0.x), pack2(b0.y), pack2(b0.z), pack2(b0.w),
                     pack2(b1.x), pack2(b1.y), pack2(b1.z), pack2(b1.w)};
#pragma unroll
        for (int c = 0; c < 8; ++c) {
            fma2(acc[0][c], a0, bb[c]);
            fma2(acc[1][c], a1, bb[c]);
            fma2(acc[2][c], a2, bb[c]);
            fma2(acc[3][c], a3, bb[c]);
        }
    }
}
template <int K>
__device__ __forceinline__ void mm4x8(const float* __restrict__ As,
                                      const float* __restrict__ Bs,
                                      int rg, int c0, ull acc[4][4]) {
#pragma unroll 4
    for (int k = 0; k < K; ++k) {
        const float* ar = As + k * 130 + rg;
        ull a0 = pack2(ar[0]);
        ull a1 = pack2(ar[32]);
        ull a2 = pack2(ar[64]);
        ull a3 = pack2(ar[96]);
        const float* br = Bs + k * 128 + c0;
        ulonglong2 b01 = *(const ulonglong2*)br;
        ulonglong2 b23 = *(const ulonglong2*)(br + 4);
        ull bb[4] = {b01.x, b01.y, b23.x, b23.y};
#pragma unroll
        for (int p = 0; p < 4; ++p) {
            fma2(acc[0][p], a0, bb[p]);
            fma2(acc[1][p], a1, bb[p]);
            fma2(acc[2][p], a2, bb[p]);
            fma2(acc[3][p], a3, bb[p]);
        }
    }
}

// ---------------- sort chain ----------------
extern "C" __global__ void __launch_bounds__(256)
k_count(const int* __restrict__ ei, const float* __restrict__ elen) {
    const int stride = gridDim.x * blockDim.x;
    for (int i = blockIdx.x * blockDim.x + threadIdx.x; i < EEDGES; i += stride) {
        float L = elen[i];
        if (L <= 10.0f && L >= 0.0f)
            atomicAdd(&g_hist[ei[EEDGES + i]], 1);
    }
}

extern "C" __global__ void __launch_bounds__(1024)
k_scan() {
    __shared__ int wsum[32];
    const int tid = threadIdx.x;
    const int lane = tid & 31, wid = tid >> 5;
    int running = 0;
    for (int base = 0; base < NNODES; base += 1024) {
        int idx = base + tid;
        int v = (idx < NNODES) ? g_hist[idx] : 0;
        int x = v;
#pragma unroll
        for (int o = 1; o < 32; o <<= 1) {
            int t = __shfl_up_sync(0xffffffffu, x, o);
            if (lane >= o) x += t;
        }
        if (lane == 31) wsum[wid] = x;
        __syncthreads();
        if (wid == 0) {
            int w = wsum[lane];
#pragma unroll
            for (int o = 1; o < 32; o <<= 1) {
                int t = __shfl_up_sync(0xffffffffu, w, o);
                if (lane >= o) w += t;
            }
            wsum[lane] = w;
        }
        __syncthreads();
        int woff = wid ? wsum[wid - 1] : 0;
        if (idx < NNODES) g_off[idx] = running + woff + x - v;
        running += wsum[31];
        __syncthreads();
    }
    if (tid == 0) g_cnt = running;
}

extern "C" __global__ void __launch_bounds__(256)
k_scatter(const int* __restrict__ ei, const float* __restrict__ elen) {
    const int stride = gridDim.x * blockDim.x;
    for (int i = blockIdx.x * blockDim.x + threadIdx.x; i < EEDGES; i += stride) {
        float L = elen[i];
        if (L <= 10.0f && L >= 0.0f) {
            int d = ei[EEDGES + i];
            int pos = atomicAdd(&g_off[d], 1);
            float C = 0.5f * (__cosf(L * (FPI / 10.0f)) + 1.0f);
            g_edge[pos] = make_int4(i, ei[i], d, __float_as_int(C));
        }
    }
}

extern "C" __global__ void k_nop() {}

// ---------------- Kernel 1: h = x @ lin1_w, zero g_agg + g_hist ----------------
extern "C" __global__ void __launch_bounds__(256, 2)
k_proj_zero(const float* __restrict__ x, const float* __restrict__ w1) {
    extern __shared__ float smf[];
    float* sX = smf;
    const int tid = threadIdx.x;
    const int cg = tid >> 4, rg = tid & 15;
    const int c0 = cg * 8, rg2 = rg * 2;

    const int ntiles = (NNODES + 127) / 128;
    for (int tile = blockIdx.x; tile < ntiles; tile += gridDim.x) {
        const int r0 = tile * 128;
        __syncthreads();
        {
            int e = tid >> 1, k0 = (tid & 1) << 6;
            int r = r0 + e;
            if (r < NNODES) {
                const float* src = x + (size_t)r * DHID + k0;
#pragma unroll
                for (int i = 0; i < 16; ++i) {
                    float4 v = ldcs4(src + 4 * i);
                    int k = k0 + 4 * i;
                    sX[(k + 0) * 130 + e] = v.x;
                    sX[(k + 1) * 130 + e] = v.y;
                    sX[(k + 2) * 130 + e] = v.z;
                    sX[(k + 3) * 130 + e] = v.w;
                }
            }
        }
        __syncthreads();
        ull acc[4][8];
#pragma unroll
        for (int j = 0; j < 4; ++j)
#pragma unroll
            for (int c = 0; c < 8; ++c) acc[j][c] = 0ull;
        mm8x8g<DHID>(sX, w1, rg2, c0, acc);
#pragma unroll
        for (int j = 0; j < 4; ++j) {
            int r = r0 + rg2 + 32 * j;
            float2 v0 = unpack2(acc[j][0]), v1 = unpack2(acc[j][1]);
            float2 v2 = unpack2(acc[j][2]), v3 = unpack2(acc[j][3]);
            float2 v4 = unpack2(acc[j][4]), v5 = unpack2(acc[j][5]);
            float2 v6 = unpack2(acc[j][6]), v7 = unpack2(acc[j][7]);
            if (r < NNODES) {
                *(float4*)(g_h + (size_t)r * DNF + c0) = make_float4(v0.x, v1.x, v2.x, v3.x);
                *(float4*)(g_h + (size_t)r * DNF + c0 + 4) = make_float4(v4.x, v5.x, v6.x, v7.x);
                *(float4*)(g_agg + (size_t)r * DNF + c0) = make_float4(0.f, 0.f, 0.f, 0.f);
                *(float4*)(g_agg + (size_t)r * DNF + c0 + 4) = make_float4(0.f, 0.f, 0.f, 0.f);
                if (cg == 0) g_hist[r] = 0;
            }
            if (r + 1 < NNODES) {
                *(float4*)(g_h + (size_t)(r + 1) * DNF + c0) = make_float4(v0.y, v1.y, v2.y, v3.y);
                *(float4*)(g_h + (size_t)(r + 1) * DNF + c0 + 4) = make_float4(v4.y, v5.y, v6.y, v7.y);
                *(float4*)(g_agg + (size_t)(r + 1) * DNF + c0) = make_float4(0.f, 0.f, 0.f, 0.f);
                *(float4*)(g_agg + (size_t)(r + 1) * DNF + c0 + 4) = make_float4(0.f, 0.f, 0.f, 0.f);
                if (cg == 0) g_hist[r + 1] = 0;
            }
        }
    }
}

// ------ Kernel 2: fp16 B-split HMMA edge MLP (2-term, staged epilogue, 3 bars) ------
#define ST64 72
#define ST128 136
#define OFF_B1  0
#define OFF_B2  512
#define OFF_W1H 1024
#define OFF_W1L (OFF_W1H + 128 * ST64 * 2)      // 19456
#define OFF_W2H (OFF_W1L + 128 * ST64 * 2)      // 37888
#define OFF_W2L (OFF_W2H + 128 * ST128 * 2)     // 72704
#define OFF_SA  (OFF_W2L + 128 * ST128 * 2)     // 107520
#define OFF_ST  (OFF_SA + 128 * ST64 * 2)       // 125952
#define OFF_STAGE (OFF_ST + 128 * ST128 * 2)    // 160768
#define SMEM_EDGE (OFF_STAGE + 128 * 132 * 4)   // 228352 B

extern "C" __global__ void __launch_bounds__(1024, 1)
k_edge(const float* __restrict__ edge_attr,
       const float* __restrict__ w1, const float* __restrict__ b1,
       const float* __restrict__ w2, const float* __restrict__ b2) {
    extern __shared__ __align__(16) char sm[];
    float* sB1 = (float*)(sm + OFF_B1);
    float* sB2 = (float*)(sm + OFF_B2);
    float* stage = (float*)(sm + OFF_STAGE);    // [128][132] f32

    const int tid = threadIdx.x;
    const int lane = tid & 31, wid = tid >> 5;
    const int g = lane >> 2, t = lane & 3;
    const int mw = (wid & 7) * 16;              // row strip (8 strips)
    const int nw = (wid >> 3) * 32;             // col quarter (4 quarters)

    // ldmatrix lane addressing: A/T fragments (row-major 16x16)
    const int arow = mw + (lane & 7) + ((lane >> 3) & 1) * 8;
    const int acol = ((lane >> 4) & 1) * 8;
    const uint sbase = (uint)__cvta_generic_to_shared(sm);
    const uint aSA = sbase + OFF_SA + (uint)((arow * ST64 + acol) * 2);
    const uint aST = sbase + OFF_ST + (uint)((arow * ST128 + acol) * 2);

    // ldmatrix lane addressing: B fragments ([n][k] storage)
    const int bn = (lane & 7) + ((lane >> 4) & 1) * 8;
    const int bk = ((lane >> 3) & 1) * 8;
    const uint aW1H0 = sbase + OFF_W1H + (uint)(((nw + bn) * ST64 + bk) * 2);
    const uint aW1H1 = sbase + OFF_W1H + (uint)(((nw + 16 + bn) * ST64 + bk) * 2);
    const uint aW1L0 = sbase + OFF_W1L + (uint)(((nw + bn) * ST64 + bk) * 2);
    const uint aW1L1 = sbase + OFF_W1L + (uint)(((nw + 16 + bn) * ST64 + bk) * 2);
    const uint aW2H0 = sbase + OFF_W2H + (uint)(((nw + bn) * ST128 + bk) * 2);
    const uint aW2H1 = sbase + OFF_W2H + (uint)(((nw + 16 + bn) * ST128 + bk) * 2);
    const uint aW2L0 = sbase + OFF_W2L + (uint)(((nw + bn) * ST128 + bk) * 2);
    const uint aW2L1 = sbase + OFF_W2L + (uint)(((nw + 16 + bn) * ST128 + bk) * 2);

    // ---- prologue: weights (transposed, fp16 hi/lo split) + biases ----
    for (int idx = tid; idx < DNG * DNF; idx += 1024) {    // w1[k][f] -> sW1[f][k]
        int k = idx >> 7, f = idx & 127;
        float v = w1[idx];
        __half h = __float2half_rn(v);
        __half l = __float2half_rn(v - __half2float(h));
        ((__half*)(sm + OFF_W1H))[f * ST64 + k] = h;
        ((__half*)(sm + OFF_W1L))[f * ST64 + k] = l;
    }
    for (int idx = tid; idx < DNF * DNF; idx += 1024) {    // w2[f1][f2] -> sW2[f2][f1]
        int f1 = idx >> 7, f2 = idx & 127;
        float v = w2[idx];
        __half h = __float2half_rn(v);
        __half l = __float2half_rn(v - __half2float(h));
        ((__half*)(sm + OFF_W2H))[f2 * ST128 + f1] = h;
        ((__half*)(sm + OFF_W2L))[f2 * ST128 + f1] = l;
    }
    if (tid < DNF) { sB1[tid] = b1[tid]; sB2[tid] = b2[tid]; }

    const int cnt = g_cnt;
    const int ntiles = (cnt + 127) >> 7;
    const int stride = gridDim.x;

    const int le = tid >> 3, lk0 = (tid & 7) << 3;   // A-load: 8 floats/thread

    auto ldg_tile = [&](int tile, float4 pf[2]) {
        int gi = (tile << 7) + le;
        int eid = (gi < cnt) ? __ldg(&g_edge[gi]).x : 0;
        const float* src = edge_attr + (size_t)eid * DNG + lk0;
        pf[0] = ldcs4(src);
        pf[1] = ldcs4(src + 4);
    };
    auto sts_tile = [&](const float4 pf[2]) {
        uint* d = (uint*)(sm + OFF_SA) + (le * ST64 + lk0) / 2;
        d[0] = h2bits(pf[0].x, pf[0].y);
        d[1] = h2bits(pf[0].z, pf[0].w);
        d[2] = h2bits(pf[1].x, pf[1].y);
        d[3] = h2bits(pf[1].z, pf[1].w);
    };

    int tile = blockIdx.x;
    if (tile < ntiles) {
        float4 pf[2];
        ldg_tile(tile, pf);
        sts_tile(pf);
    }
    __syncthreads();

    for (; tile < ntiles; tile += stride) {
        const int eg0 = tile << 7;

        // ---- GEMM1 (K=64): D1 = A*W1h + A*W1l ----
        float d1[4][4];
#pragma unroll
        for (int nt = 0; nt < 4; ++nt)
#pragma unroll
            for (int q = 0; q < 4; ++q) d1[nt][q] = 0.0f;
#pragma unroll
        for (int kc = 0; kc < 4; ++kc) {
            uint a0, a1, a2, a3;
            ldsm4(a0, a1, a2, a3, aSA + kc * 32);
#pragma unroll
            for (int p = 0; p < 2; ++p) {
                uint bh0, bh1, bh2, bh3, bl0, bl1, bl2, bl3;
                ldsm4(bh0, bh1, bh2, bh3, (p ? aW1H1 : aW1H0) + kc * 32);
                ldsm4(bl0, bl1, bl2, bl3, (p ? aW1L1 : aW1L0) + kc * 32);
                mma_f16(d1[2 * p], a0, a1, a2, a3, bh0, bh1);
                mma_f16(d1[2 * p], a0, a1, a2, a3, bl0, bl1);
                mma_f16(d1[2 * p + 1], a0, a1, a2, a3, bh2, bh3);
                mma_f16(d1[2 * p + 1], a0, a1, a2, a3, bl2, bl3);
            }
        }
        __syncthreads();   // bar1: sA reads done

        // ---- prefetch next tile's A ----
        const int tnext = tile + stride;
        const bool have = tnext < ntiles;
        float4 pf[2];
        if (have) ldg_tile(tnext, pf);

        // ---- ssp(D1 + b1) -> sT (fp16) ----
#pragma unroll
        for (int nt = 0; nt < 4; ++nt) {
            int c = nw + nt * 8 + 2 * t;
            float b0v = sB1[c], b1v = sB1[c + 1];
            *(uint*)(sm + OFF_ST + ((mw + g) * ST128 + c) * 2) =
                h2bits(ssp_f(d1[nt][0] + b0v), ssp_f(d1[nt][1] + b1v));
            *(uint*)(sm + OFF_ST + ((mw + g + 8) * ST128 + c) * 2) =
                h2bits(ssp_f(d1[nt][2] + b0v), ssp_f(d1[nt][3] + b1v));
        }
        __syncthreads();   // bar2: sT ready

        // ---- GEMM2 (K=128): D2 = T*W2h + T*W2l ----
        float d2[4][4];
#pragma unroll
        for (int nt = 0; nt < 4; ++nt)
#pragma unroll
            for (int q = 0; q < 4; ++q) d2[nt][q] = 0.0f;
#pragma unroll
        for (int kc = 0; kc < 8; ++kc) {
            uint a0, a1, a2, a3;
            ldsm4(a0, a1, a2, a3, aST + kc * 32);
#pragma unroll
            for (int p = 0; p < 2; ++p) {
                uint bh0, bh1, bh2, bh3, bl0, bl1, bl2, bl3;
                ldsm4(bh0, bh1, bh2, bh3, (p ? aW2H1 : aW2H0) + kc * 32);
                ldsm4(bl0, bl1, bl2, bl3, (p ? aW2L1 : aW2L0) + kc * 32);
                mma_f16(d2[2 * p], a0, a1, a2, a3, bh0, bh1);
                mma_f16(d2[2 * p], a0, a1, a2, a3, bl0, bl1);
                mma_f16(d2[2 * p + 1], a0, a1, a2, a3, bh2, bh3);
                mma_f16(d2[2 * p + 1], a0, a1, a2, a3, bl2, bl3);
            }
        }

        // ---- stage D2 (separate buffer: prev epilogue ordered before via bar1) ----
#pragma unroll
        for (int nt = 0; nt < 4; ++nt) {
            int c = nw + nt * 8 + 2 * t;
            *(float2*)(stage + (mw + g) * 132 + c) = make_float2(d2[nt][0], d2[nt][1]);
            *(float2*)(stage + (mw + g + 8) * 132 + c) = make_float2(d2[nt][2], d2[nt][3]);
        }
        // ---- store prefetched A (sA free since bar1) ----
        if (have) sts_tile(pf);
        __syncthreads();   // bar3: stage + sA ready

        // ---- epilogue: pair/thread, dst-merged v4 REDs (overlaps next GEMM1) ----
        {
            int pe = tid >> 4;                 // edge pair 0..63
            int c0 = (tid & 15) * 8;           // 8 cols
            int e0 = 2 * pe, e1 = 2 * pe + 1;
            int gi0 = eg0 + e0, gi1 = eg0 + e1;
            int4 ed0 = __ldg(&g_edge[gi0]);
            int4 ed1 = __ldg(&g_edge[gi1]);
            float cv0 = __int_as_float(ed0.w);
            float cv1 = __int_as_float(ed1.w);
            bool ok0 = (gi0 < cnt) && (cv0 != 0.0f);
            bool ok1 = (gi1 < cnt) && (cv1 != 0.0f);
            float m0[8], m1[8];
            if (ok0) {
                const float* hp = g_h + (size_t)ed0.y * DNF + c0;
#pragma unroll
                for (int q = 0; q < 2; ++q) {
                    float4 s = *(float4*)(stage + e0 * 132 + c0 + 4 * q);
                    float4 bb = *(float4*)(sB2 + c0 + 4 * q);
                    float4 hv = ldcg4(hp + 4 * q);
                    m0[4 * q + 0] = (s.x + bb.x) * cv0 * hv.x;
                    m0[4 * q + 1] = (s.y + bb.y) * cv0 * hv.y;
                    m0[4 * q + 2] = (s.z + bb.z) * cv0 * hv.z;
                    m0[4 * q + 3] = (s.w + bb.w) * cv0 * hv.w;
                }
            }
            if (ok1) {
                const float* hp = g_h + (size_t)ed1.y * DNF + c0;
#pragma unroll
                for (int q = 0; q < 2; ++q) {
                    float4 s = *(float4*)(stage + e1 * 132 + c0 + 4 * q);
                    float4 bb = *(float4*)(sB2 + c0 + 4 * q);
                    float4 hv = ldcg4(hp + 4 * q);
                    m1[4 * q + 0] = (s.x + bb.x) * cv1 * hv.x;
                    m1[4 * q + 1] = (s.y + bb.y) * cv1 * hv.y;
                    m1[4 * q + 2] = (s.z + bb.z) * cv1 * hv.z;
                    m1[4 * q + 3] = (s.w + bb.w) * cv1 * hv.w;
                }
            }
            if (ok0 && ok1 && ed0.z == ed1.z) {
                float* dp = g_agg + (size_t)ed0.z * DNF + c0;
                red_add_v4(dp, m0[0] + m1[0], m0[1] + m1[1], m0[2] + m1[2], m0[3] + m1[3]);
                red_add_v4(dp + 4, m0[4] + m1[4], m0[5] + m1[5], m0[6] + m1[6], m0[7] + m1[7]);
            } else {
                if (ok0) {
                    float* dp = g_agg + (size_t)ed0.z * DNF + c0;
                    red_add_v4(dp, m0[0], m0[1], m0[2], m0[3]);
                    red_add_v4(dp + 4, m0[4], m0[5], m0[6], m0[7]);
                }
                if (ok1) {
                    float* dp = g_agg + (size_t)ed1.z * DNF + c0;
                    red_add_v4(dp, m1[0], m1[1], m1[2], m1[3]);
                    red_add_v4(dp + 4, m1[4], m1[5], m1[6], m1[7]);
                }
            }
        }
        // epilogue reads stage/global only; next GEMM1 (sA) proceeds, ordered by bar1.
    }
}

// -------- Kernel 3: out = ssp(agg@lin2_w + lin2_b) @ lin_w + lin_b --------
extern "C" __global__ void __launch_bounds__(512, 1)
k_out(const float* __restrict__ w2, const float* __restrict__ b2,
      const float* __restrict__ w3, const float* __restrict__ b3,
      float* __restrict__ out) {
    extern __shared__ float smf[];
    float* sW2 = smf;
    float* sW3 = sW2 + DNF * DHID;
    float* sA  = sW3 + DHID * DHID;
    float* sB2 = sA + DNF * 130;
    float* sB3 = sB2 + 128;

    const int tid = threadIdx.x;
    const int rg = tid & 31, cg = tid >> 5;
    const int c0 = cg * 8;

    for (int i = tid; i < DNF * DHID / 4; i += 512)
        ((float4*)sW2)[i] = ((const float4*)w2)[i];
    for (int i = tid; i < DHID * DHID / 4; i += 512)
        ((float4*)sW3)[i] = ((const float4*)w3)[i];
    if (tid < DHID) { sB2[tid] = b2[tid]; sB3[tid] = b3[tid]; }

    const int ntiles = (NNODES + 127) / 128;
    for (int tile = blockIdx.x; tile < ntiles; tile += gridDim.x) {
        const int r0 = tile * 128;
        __syncthreads();
        {
            int e = tid >> 2, k0 = (tid & 3) << 5;
            int r = r0 + e;
            const float* src = g_agg + (size_t)r * DNF + k0;
#pragma unroll
            for (int i = 0; i < 8; ++i) {
                float4 v = (r < NNODES) ? ldcs4(src + 4 * i) : make_float4(0.f, 0.f, 0.f, 0.f);
                int k = k0 + 4 * i;
                sA[(k + 0) * 130 + e] = v.x;
                sA[(k + 1) * 130 + e] = v.y;
                sA[(k + 2) * 130 + e] = v.z;
                sA[(k + 3) * 130 + e] = v.w;
            }
        }
        __syncthreads();

        ull acc[4][4];
#pragma unroll
        for (int j = 0; j < 4; ++j)
#pragma unroll
            for (int p = 0; p < 4; ++p) acc[j][p] = 0ull;
        mm4x8<DNF>(sA, sW2, rg, c0, acc);
        __syncthreads();

#pragma unroll
        for (int p = 0; p < 4; ++p) {
            float bx = sB2[c0 + 2 * p], by = sB2[c0 + 2 * p + 1];
#pragma unroll
            for (int j = 0; j < 4; ++j) {
                float2 v = unpack2(acc[j][p]);
                int row = rg + 32 * j;
                sA[(c0 + 2 * p) * 130 + row] = ssp_f(v.x + bx);
                sA[(c0 + 2 * p + 1) * 130 + row] = ssp_f(v.y + by);
            }
        }
        __syncthreads();

#pragma unroll
        for (int j = 0; j < 4; ++j)
#pragma unroll
            for (int p = 0; p < 4; ++p) acc[j][p] = 0ull;
        mm4x8<DHID>(sA, sW3, rg, c0, acc);

#pragma unroll
        for (int j = 0; j < 4; ++j) {
            int r = r0 + rg + 32 * j;
            if (r < NNODES) {
                float2 v0 = unpack2(acc[j][0]), v1 = unpack2(acc[j][1]);
                float2 v2 = unpack2(acc[j][2]), v3 = unpack2(acc[j][3]);
                *(float4*)(out + (size_t)r * DHID + c0) =
                    make_float4(v0.x + sB3[c0 + 0], v0.y + sB3[c0 + 1],
                                v1.x + sB3[c0 + 2], v1.y + sB3[c0 + 3]);
                *(float4*)(out + (size_t)r * DHID + c0 + 4) =
                    make_float4(v2.x + sB3[c0 + 4], v2.y + sB3[c0 + 5],
                                v3.x + sB3[c0 + 6], v3.y + sB3[c0 + 7]);
            }
        }
    }
}

extern "C" void kernel_launch(void* const* d_in, const int* in_sizes, int n_in,
                              void* d_out, int out_size) {
    const float* x      = (const float*)d_in[0];
    const int*   ei     = (const int*)d_in[1];
    const float* elen   = (const float*)d_in[2];
    const float* eattr  = (const float*)d_in[3];
    const float* lin1_w = (const float*)d_in[4];
    const float* nn_w1  = (const float*)d_in[5];
    const float* nn_b1  = (const float*)d_in[6];
    const float* nn_w2  = (const float*)d_in[7];
    const float* nn_b2  = (const float*)d_in[8];
    const float* lin2_w = (const float*)d_in[9];
    const float* lin2_b = (const float*)d_in[10];
    const float* lin_w  = (const float*)d_in[11];
    const float* lin_b  = (const float*)d_in[12];
    float* out = (float*)d_out;

    size_t sm1 = (size_t)(DHID * 130) * 4;
    size_t sm3 = (size_t)(DNF * DHID + DHID * DHID + DNF * 130 + 2 * 128) * 4;

    cudaFuncSetAttribute(k_proj_zero, cudaFuncAttributeMaxDynamicSharedMemorySize, (int)sm1);
    cudaFuncSetAttribute(k_edge, cudaFuncAttributeMaxDynamicSharedMemorySize, SMEM_EDGE);
    cudaFuncSetAttribute(k_out, cudaFuncAttributeMaxDynamicSharedMemorySize, (int)sm3);

    k_proj_zero<<<304, 256, sm1>>>(x, lin1_w);   // 1
    k_count<<<304, 256>>>(ei, elen);             // 2
    k_scan<<<1, 1024>>>();                       // 3
    k_scatter<<<304, 256>>>(ei, elen);           // 4
    k_nop<<<1, 32>>>();                          // 5
    k_edge<<<152, 1024, SMEM_EDGE>>>(eattr, nn_w1, nn_b1, nn_w2, nn_b2);  // 6
    k_out<<<152, 512, sm3>>>(lin2_w, lin2_b, lin_w, lin_b, out);
}